// round 17
// baseline (speedup 1.0000x reference)
#include <cuda_runtime.h>
#include <cstdint>
#include <mma.h>

using namespace nvcuda;

#define B_  4
#define S_  2048
#define D_  1024
#define H_  16
#define HD  64
#define M_TOT (B_ * S_)

// Scratch (allocation-free per harness rules)
__device__ float g_q[B_ * H_ * S_ * HD];   // [B,H,S,Hd]  tf32-rounded
__device__ float g_k[B_ * H_ * S_ * HD];   // [B,H,S,Hd]
__device__ float g_vt[B_ * H_ * HD * S_];  // [B,H,Hd,S]  (transposed V)
__device__ float g_y[M_TOT * D_];          // attention out (tf32-rounded)
__device__ float g_xr[M_TOT * D_];         // tf32-rounded x       [M][K]
__device__ float g_wqkvt[3 * D_ * D_];     // tf32-rounded w_qkv^T [N][K]
__device__ float g_wprojt[D_ * D_];        // tf32-rounded w_proj^T[N][K]

__device__ __forceinline__ float tf32r(float x) { return wmma::__float_to_tf32(x); }

__global__ __launch_bounds__(256)
void round_kernel(const float* __restrict__ in, float* __restrict__ out, int n4)
{
    int i = blockIdx.x * blockDim.x + threadIdx.x;
    if (i < n4) {
        float4 v = ((const float4*)in)[i];
        v.x = tf32r(v.x); v.y = tf32r(v.y); v.z = tf32r(v.z); v.w = tf32r(v.w);
        ((float4*)out)[i] = v;
    }
}

// in [K][N] fp32 -> out [N][K] tf32-rounded (tiled transpose)
__global__ __launch_bounds__(256)
void tround_kernel(const float* __restrict__ in, float* __restrict__ out,
                   int K, int N)
{
    __shared__ float t[32][33];
    const int n0 = blockIdx.x * 32;
    const int k0 = blockIdx.y * 32;
    const int tx = threadIdx.x, ty = threadIdx.y;
    #pragma unroll
    for (int i = 0; i < 4; i++)
        t[ty + i * 8][tx] = in[(size_t)(k0 + ty + i * 8) * N + n0 + tx];
    __syncthreads();
    #pragma unroll
    for (int i = 0; i < 4; i++)
        out[(size_t)(n0 + ty + i * 8) * K + k0 + tx] = tf32r(t[tx][ty + i * 8]);
}

// ---------------------------------------------------------------------------
__device__ __forceinline__ void cpasync16(void* smem, const void* gmem) {
    unsigned s = (unsigned)__cvta_generic_to_shared(smem);
    asm volatile("cp.async.cg.shared.global [%0], [%1], 16;\n" :: "r"(s), "l"(gmem));
}
#define CP_COMMIT() asm volatile("cp.async.commit_group;\n" ::: "memory")
#define CP_WAIT0()  asm volatile("cp.async.wait_group 0;\n" ::: "memory")
#define CP_WAIT1()  asm volatile("cp.async.wait_group 1;\n" ::: "memory")

__device__ __forceinline__ void ldsm_x4(uint32_t addr, uint32_t& r0, uint32_t& r1,
                                        uint32_t& r2, uint32_t& r3) {
    asm volatile("ldmatrix.sync.aligned.m8n8.x4.shared.b16 {%0,%1,%2,%3}, [%4];"
                 : "=r"(r0), "=r"(r1), "=r"(r2), "=r"(r3) : "r"(addr));
}

__device__ __forceinline__ void mma_tf32(float& d0, float& d1, float& d2, float& d3,
                                         uint32_t a0, uint32_t a1, uint32_t a2, uint32_t a3,
                                         uint32_t b0, uint32_t b1) {
    asm volatile(
        "mma.sync.aligned.m16n8k8.row.col.f32.tf32.tf32.f32 "
        "{%0,%1,%2,%3}, {%4,%5,%6,%7}, {%8,%9}, {%0,%1,%2,%3};"
        : "+f"(d0), "+f"(d1), "+f"(d2), "+f"(d3)
        : "r"(a0), "r"(a1), "r"(a2), "r"(a3), "r"(b0), "r"(b1));
}

// ---------------------------------------------------------------------------
// TF32 GEMM via ldmatrix + raw mma. C = A[M,K] @ Wt[N,K]^T, K=1024.
// Block tile 128x128, BK=32, 3-stage cp.async pipeline with the next-stage
// issue HOISTED ahead of the compute burst (DMA overlaps all 88 LDSM/MMA ops).
// 256 thr = 8 warps (4x2), warp tile 32x64.
// mode 0: scatter q/k ([B,H,S,Hd]) and v transposed ([B,H,Hd,S]); mode 1: store.
// ---------------------------------------------------------------------------
#define BM 128
#define BN 128
#define BK 32
#define LDA 36
#define LDB 36
#define LDC 68
#define G_STAGE_F (BM * LDA + BN * LDB)            // 9216 floats
#define G_STAGE_B (G_STAGE_F * 4)                  // 36864
#define G_SMEM_B  (3 * G_STAGE_B)                  // 110592

__global__ __launch_bounds__(256, 2)
void gemm_tf32_kernel(const float* __restrict__ A,
                      const float* __restrict__ Wt,
                      float* __restrict__ Cout,
                      int N, int mode)
{
    extern __shared__ __align__(16) char gsm[];
    const uint32_t smem_base = (uint32_t)__cvta_generic_to_shared(gsm);
    const int K = D_;

    const int tid  = threadIdx.x;
    const int wid  = tid >> 5;
    const int lane = tid & 31;
    const int wm   = wid >> 1;
    const int wn   = wid & 1;
    const int m0   = blockIdx.y * BM;
    const int n0   = blockIdx.x * BN;

    const int a_row = (lane & 7) + 8 * ((lane >> 3) & 1);
    const int a_k   = 4 * ((lane >> 4) & 1);
    const int b_row = (lane & 7) + 8 * ((lane >> 4) & 1);
    const int b_k   = 4 * ((lane >> 3) & 1);
    int aoff[2], boff[4];
    #pragma unroll
    for (int mi = 0; mi < 2; mi++)
        aoff[mi] = (wm * 32 + mi * 16 + a_row) * LDA + a_k;
    #pragma unroll
    for (int ni = 0; ni < 4; ni++)
        boff[ni] = BM * LDA + (wn * 64 + ni * 16 + b_row) * LDB + b_k;

    float c[2][8][4];
    #pragma unroll
    for (int mi = 0; mi < 2; mi++)
        #pragma unroll
        for (int nj = 0; nj < 8; nj++)
            #pragma unroll
            for (int e = 0; e < 4; e++)
                c[mi][nj][e] = 0.0f;

    auto issue = [&](int it, int s) {
        float* As = (float*)(gsm + s * G_STAGE_B);
        float* Bs = As + BM * LDA;
        int k0 = it * BK;
        #pragma unroll
        for (int i = 0; i < 4; i++) {
            int idx = tid + i * 256;    // 0..1023
            int r   = idx >> 3;         // 0..127
            int c4  = idx & 7;          // 0..7
            cpasync16(As + r * LDA + c4 * 4, A  + (size_t)(m0 + r) * K + k0 + c4 * 4);
        }
        #pragma unroll
        for (int i = 0; i < 4; i++) {
            int idx = tid + i * 256;
            int r   = idx >> 3;
            int c4  = idx & 7;
            cpasync16(Bs + r * LDB + c4 * 4, Wt + (size_t)(n0 + r) * K + k0 + c4 * 4);
        }
        CP_COMMIT();
    };

    const int nIt = K / BK;    // 32
    issue(0, 0);
    issue(1, 1);

    for (int it = 0; it < nIt; it++) {
        const int s = it % 3;
        if (it + 1 < nIt) CP_WAIT1(); else CP_WAIT0();
        __syncthreads();

        // HOISTED: start DMA for stage it+2 before the compute burst.
        // Buffer (it+2)%3 was consumed in iteration it-1 (all warps passed
        // that compute before this sync), so the overwrite is safe.
        if (it + 2 < nIt) issue(it + 2, (it + 2) % 3);

        const uint32_t st = smem_base + s * G_STAGE_B;
        #pragma unroll
        for (int kk = 0; kk < BK; kk += 8) {
            uint32_t a[2][4], b[4][4];
            #pragma unroll
            for (int mi = 0; mi < 2; mi++)
                ldsm_x4(st + (aoff[mi] + kk) * 4, a[mi][0], a[mi][1], a[mi][2], a[mi][3]);
            #pragma unroll
            for (int ni = 0; ni < 4; ni++)
                ldsm_x4(st + (boff[ni] + kk) * 4, b[ni][0], b[ni][1], b[ni][2], b[ni][3]);
            #pragma unroll
            for (int mi = 0; mi < 2; mi++)
                #pragma unroll
                for (int nj = 0; nj < 8; nj++)
                    mma_tf32(c[mi][nj][0], c[mi][nj][1], c[mi][nj][2], c[mi][nj][3],
                             a[mi][0], a[mi][1], a[mi][2], a[mi][3],
                             b[nj >> 1][2 * (nj & 1)], b[nj >> 1][2 * (nj & 1) + 1]);
        }
    }
    __syncthreads();

    float* Cs = (float*)gsm;
    #pragma unroll
    for (int h = 0; h < 2; h++) {
        if (wn == h) {
            #pragma unroll
            for (int mi = 0; mi < 2; mi++)
                #pragma unroll
                for (int nj = 0; nj < 8; nj++) {
                    int r  = wm * 32 + mi * 16 + (lane >> 2);
                    int cc = nj * 8 + (lane & 3) * 2;
                    *(float2*)(Cs + r * LDC + cc)       = make_float2(c[mi][nj][0], c[mi][nj][1]);
                    *(float2*)(Cs + (r + 8) * LDC + cc) = make_float2(c[mi][nj][2], c[mi][nj][3]);
                }
        }
        __syncthreads();

        const int col0 = n0 + h * 64;
        if (mode == 0 && (col0 >> 10) == 2) {
            // V half-tile: transposed write -> g_vt [B,H,Hd,S], coalesced over s
            #pragma unroll
            for (int e = 0; e < 32; e++) {
                int idx = tid + e * 256;        // 0..8191
                int dl  = idx >> 7;             // 0..63 (local col)
                int sl  = idx & 127;            // 0..127 (local row)
                int col = col0 + dl;
                int rem = col & 1023;
                int hh  = rem >> 6;
                int d   = rem & 63;
                int row = m0 + sl;
                int bb  = row >> 11;
                int ss  = row & 2047;
                g_vt[(((size_t)(bb * H_ + hh)) * HD + d) * S_ + ss] =
                    tf32r(Cs[sl * LDC + dl]);
            }
        } else {
            #pragma unroll
            for (int e = 0; e < 32; e++) {
                int idx = tid + e * 256;
                int r   = idx >> 6;
                int cc  = idx & 63;
                float val = Cs[r * LDC + cc];
                int row = m0 + r;
                int col = col0 + cc;
                if (mode == 0) {
                    int part = col >> 10;       // 0 or 1 here
                    int rem  = col & 1023;
                    int hh   = rem >> 6;
                    int d    = rem & 63;
                    int bb   = row >> 11;
                    int ss   = row & 2047;
                    float* dst = (part == 0) ? g_q : g_k;
                    dst[(((size_t)(bb * H_ + hh)) * S_ + ss) * HD + d] = tf32r(val);
                } else {
                    Cout[(size_t)row * N + col] = val;
                }
            }
        }
        __syncthreads();
    }
}

// ---------------------------------------------------------------------------
// Causal flash attention, ldmatrix + raw mma (R14 structure) + LPT schedule:
// q-tile index REVERSED so the longest CTAs (most key tiles) launch first.
// Q tile 128, K tile 64, 256 thr = 8 warps.
// ---------------------------------------------------------------------------
#define KT   64
#define LDK  68
#define AK_OFF  0
#define AV_OFF  (2 * KT * LDK)
#define AQP_OFF (4 * KT * LDK)
#define A_FLOATS (AQP_OFF + 128 * LDK)
#define A_SMEM_B (A_FLOATS * 4)    // 104448

__global__ __launch_bounds__(256, 2)
void attn_kernel()
{
    extern __shared__ __align__(16) float dsm[];
    const uint32_t smem_base = (uint32_t)__cvta_generic_to_shared(dsm);

    const int qt = (int)gridDim.x - 1 - (int)blockIdx.x;   // LPT: longest first
    const int q0 = qt * 128;
    const int bh = blockIdx.y;
    const int b  = bh >> 4;
    const int h  = bh & 15;

    const float* Qg  = g_q  + ((size_t)bh * S_ + q0) * HD;
    const float* Kg  = g_k  + (size_t)bh * S_ * HD;
    const float* Vtg = g_vt + (size_t)bh * HD * S_;

    const int tid  = threadIdx.x;
    const int wm   = tid >> 5;
    const int lane = tid & 31;

    const int a_row = (lane & 7) + 8 * ((lane >> 3) & 1);
    const int a_k   = 4 * ((lane >> 4) & 1);
    const int b_row = (lane & 7) + 8 * ((lane >> 4) & 1);
    const int b_k   = 4 * ((lane >> 3) & 1);

    const int qbase  = q0 + wm * 16 + (lane >> 2);
    const int c_base = (lane & 3) * 2;

    // --- Load Q tile (128x64 = 2048 float4) into smem QP region ---
    {
        float* Qs = dsm + AQP_OFF;
        #pragma unroll
        for (int i = 0; i < 8; i++) {
            int idx = tid + i * 256;    // 0..2047
            int r   = idx >> 4;         // 0..127
            int c4  = idx & 15;         // 0..15
            cpasync16(Qs + r * LDK + c4 * 4, Qg + (size_t)r * HD + c4 * 4);
        }
        CP_COMMIT(); CP_WAIT0();
        __syncthreads();
    }
    uint32_t qa[8][4];
    {
        const uint32_t qwb = smem_base + (AQP_OFF + (wm * 16 + a_row) * LDK + a_k) * 4;
        #pragma unroll
        for (int kk = 0; kk < 8; kk++) {
            ldsm_x4(qwb + kk * 8 * 4, qa[kk][0], qa[kk][1], qa[kk][2], qa[kk][3]);
            #pragma unroll
            for (int i = 0; i < 4; i++)
                qa[kk][i] = __float_as_uint(__uint_as_float(qa[kk][i]) * 0.125f);
        }
    }
    __syncthreads();   // Q regs loaded; QP region becomes P staging

    float o[8][4];
    #pragma unroll
    for (int nj = 0; nj < 8; nj++)
        #pragma unroll
        for (int e = 0; e < 4; e++)
            o[nj][e] = 0.0f;

    float m_st[2] = { -1e30f, -1e30f };
    float l_st[2] = { 0.0f, 0.0f };

    auto issue_kv = [&](int j0, int bufi) {
        float* Kd = dsm + AK_OFF + bufi * (KT * LDK);
        float* Vd = dsm + AV_OFF + bufi * (KT * LDK);
        #pragma unroll
        for (int i = 0; i < 4; i++) {
            int idx = tid + i * 256;    // 0..1023
            int r   = idx >> 4;         // 0..63
            int c4  = idx & 15;         // 0..15
            cpasync16(Kd + r * LDK + c4 * 4, Kg  + (size_t)(j0 + r) * HD + c4 * 4);
            cpasync16(Vd + r * LDK + c4 * 4, Vtg + (size_t)r * S_ + j0 + c4 * 4);
        }
        CP_COMMIT();
    };

    const uint32_t pw_base = smem_base + (AQP_OFF + wm * 16 * LDK) * 4;
    float* Pw = dsm + AQP_OFF + wm * 16 * LDK;

    const int njt = 2 * qt + 2;
    issue_kv(0, 0);

    for (int jt = 0; jt < njt; jt++) {
        const int buf = jt & 1;
        const int j0  = jt * KT;
        if (jt + 1 < njt) {
            issue_kv((jt + 1) * KT, buf ^ 1);
            CP_WAIT1();
        } else {
            CP_WAIT0();
        }
        __syncthreads();

        const uint32_t kst = smem_base + (AK_OFF + buf * KT * LDK) * 4;
        const uint32_t vst = smem_base + (AV_OFF + buf * KT * LDK) * 4;

        // S = (Q*scale) @ K^T : 16x64 per warp (8 n8 frags)
        float sf[8][4];
        #pragma unroll
        for (int nj = 0; nj < 8; nj++)
            #pragma unroll
            for (int e = 0; e < 4; e++)
                sf[nj][e] = 0.0f;
        #pragma unroll
        for (int kk = 0; kk < 8; kk++) {
            uint32_t kb[4][4];
            #pragma unroll
            for (int ni = 0; ni < 4; ni++)
                ldsm_x4(kst + ((ni * 16 + b_row) * LDK + b_k + kk * 8) * 4,
                        kb[ni][0], kb[ni][1], kb[ni][2], kb[ni][3]);
            #pragma unroll
            for (int nj = 0; nj < 8; nj++)
                mma_tf32(sf[nj][0], sf[nj][1], sf[nj][2], sf[nj][3],
                         qa[kk][0], qa[kk][1], qa[kk][2], qa[kk][3],
                         kb[nj >> 1][2 * (nj & 1)], kb[nj >> 1][2 * (nj & 1) + 1]);
        }

        // Causal mask + online softmax in registers
        float mx[2] = { -1e30f, -1e30f };
        #pragma unroll
        for (int nj = 0; nj < 8; nj++) {
            #pragma unroll
            for (int e = 0; e < 4; e++) {
                int col = j0 + nj * 8 + c_base + (e & 1);
                int hv  = e >> 1;
                int row = qbase + 8 * hv;
                if (col > row) sf[nj][e] = -1e30f;
                mx[hv] = fmaxf(mx[hv], sf[nj][e]);
            }
        }
        #pragma unroll
        for (int hv = 0; hv < 2; hv++) {
            mx[hv] = fmaxf(mx[hv], __shfl_xor_sync(0xffffffff, mx[hv], 1));
            mx[hv] = fmaxf(mx[hv], __shfl_xor_sync(0xffffffff, mx[hv], 2));
        }
        float mn[2] = { fmaxf(m_st[0], mx[0]), fmaxf(m_st[1], mx[1]) };
        float al[2] = { __expf(m_st[0] - mn[0]), __expf(m_st[1] - mn[1]) };

        float ps[2] = { 0.0f, 0.0f };
        #pragma unroll
        for (int nj = 0; nj < 8; nj++) {
            #pragma unroll
            for (int e = 0; e < 4; e++) {
                int hv = e >> 1;
                float p = __expf(sf[nj][e] - mn[hv]);
                ps[hv] += p;
                sf[nj][e] = tf32r(p);
            }
        }
        #pragma unroll
        for (int hv = 0; hv < 2; hv++) {
            ps[hv] += __shfl_xor_sync(0xffffffff, ps[hv], 1);
            ps[hv] += __shfl_xor_sync(0xffffffff, ps[hv], 2);
            l_st[hv] = l_st[hv] * al[hv] + ps[hv];
            m_st[hv] = mn[hv];
        }

        // Rescale O; stage P to warp-private smem; O += P @ V
        #pragma unroll
        for (int nj = 0; nj < 8; nj++)
            #pragma unroll
            for (int e = 0; e < 4; e++)
                o[nj][e] *= al[e >> 1];

        {
            int r = lane >> 2;
            #pragma unroll
            for (int nj = 0; nj < 8; nj++) {
                int cc = nj * 8 + c_base;
                *(float2*)(Pw + r * LDK + cc)       = make_float2(sf[nj][0], sf[nj][1]);
                *(float2*)(Pw + (r + 8) * LDK + cc) = make_float2(sf[nj][2], sf[nj][3]);
            }
        }
        __syncwarp();

        #pragma unroll
        for (int kk = 0; kk < 8; kk++) {
            uint32_t pa[4], vb[4][4];
            ldsm_x4(pw_base + (a_row * LDK + a_k + kk * 8) * 4,
                    pa[0], pa[1], pa[2], pa[3]);
            #pragma unroll
            for (int ni = 0; ni < 4; ni++)
                ldsm_x4(vst + ((ni * 16 + b_row) * LDK + b_k + kk * 8) * 4,
                        vb[ni][0], vb[ni][1], vb[ni][2], vb[ni][3]);
            #pragma unroll
            for (int nj = 0; nj < 8; nj++)
                mma_tf32(o[nj][0], o[nj][1], o[nj][2], o[nj][3],
                         pa[0], pa[1], pa[2], pa[3],
                         vb[nj >> 1][2 * (nj & 1)], vb[nj >> 1][2 * (nj & 1) + 1]);
        }
        __syncthreads();   // protect K/V buffers for next iteration's cp.async
    }

    // Epilogue: normalize, tf32-round, write g_y directly (float2)
    {
        float inv[2] = { 1.0f / l_st[0], 1.0f / l_st[1] };
        #pragma unroll
        for (int hv = 0; hv < 2; hv++) {
            int row = qbase + 8 * hv;
            float* dst = g_y + ((size_t)(b * S_) + row) * D_ + h * HD;
            #pragma unroll
            for (int nj = 0; nj < 8; nj++) {
                int cc = nj * 8 + c_base;
                float2 v;
                v.x = tf32r(o[nj][2 * hv + 0] * inv[hv]);
                v.y = tf32r(o[nj][2 * hv + 1] * inv[hv]);
                *(float2*)(dst + cc) = v;
            }
        }
    }
}

// ---------------------------------------------------------------------------
extern "C" void kernel_launch(void* const* d_in, const int* in_sizes, int n_in,
                              void* d_out, int out_size)
{
    const float* x      = (const float*)d_in[0];
    const float* w_qkv  = (const float*)d_in[1];
    const float* w_proj = (const float*)d_in[2];
    float* out          = (float*)d_out;

    float *xr, *wqt, *wpt, *yr;
    cudaGetSymbolAddress((void**)&xr,  g_xr);
    cudaGetSymbolAddress((void**)&wqt, g_wqkvt);
    cudaGetSymbolAddress((void**)&wpt, g_wprojt);
    cudaGetSymbolAddress((void**)&yr,  g_y);

    cudaFuncSetAttribute(gemm_tf32_kernel,
                         cudaFuncAttributeMaxDynamicSharedMemorySize, G_SMEM_B);
    cudaFuncSetAttribute(attn_kernel,
                         cudaFuncAttributeMaxDynamicSharedMemorySize, A_SMEM_B);

    // 0) Prep
    round_kernel<<<(M_TOT * D_ / 4 + 255) / 256, 256>>>(x, xr, M_TOT * D_ / 4);
    tround_kernel<<<dim3(3 * D_ / 32, D_ / 32), dim3(32, 8)>>>(w_qkv, wqt, D_, 3 * D_);
    tround_kernel<<<dim3(D_ / 32, D_ / 32), dim3(32, 8)>>>(w_proj, wpt, D_, D_);

    // 1) QKV GEMM + scatter (q,k row-major; v transposed)
    gemm_tf32_kernel<<<dim3(3 * D_ / BN, M_TOT / BM), 256, G_SMEM_B>>>(
        xr, wqt, nullptr, 3 * D_, 0);

    // 2) Causal flash attention (LPT order)
    attn_kernel<<<dim3(S_ / 128, B_ * H_), 256, A_SMEM_B>>>();

    // 3) Output projection
    gemm_tf32_kernel<<<dim3(D_ / BN, M_TOT / BM), 256, G_SMEM_B>>>(
        yr, wpt, out, D_, 1);
}